// round 17
// baseline (speedup 1.0000x reference)
#include <cuda_runtime.h>
#include <cuda_fp16.h>
#include <cstdint>

// Problem constants
#define BB 32
#define NN 64
#define EE 4032
#define EPN 63
#define FI 4
#define NSTEP 10

// ---------------- scratch (device globals) ----------------------------------
__device__ float g_xst[BB * NN * FI];
__device__ float g_xarg[BB * NN * FI];
__device__ float g_kacc[BB * NN * FI];
__device__ float g_agg[BB * NN * 256];
// W2 quantized: per (k,ck,n): [s8 b1 x32 | s8 b0 x32]; scale = colmax
__device__ unsigned char g_w2q[2 * 8 * 256 * 64];
__device__ float g_w2s[2 * 8 * 256];
// node weights transposed: [col][j]
__device__ float g_wo1t[256 * 264];
__device__ float g_wo2t[256 * 256];

// ---------------- smem layout (bytes) ----------------------------------------
#define SM_PRE   0        // 128 x 8 f32            (4096)
#define SM_EW    4096     // 128 x 2 f32            (1024)
#define SM_B1    5120     // 2 x 256 f32            (2048)
#define SM_B2    7168     // 2 x 256 f32            (2048)
#define SM_W1    9216     // 2 x 8 x 256 f32        (16384)
#define SM_PART  25600    // 2 x 4 x 128 f32        (4096)
#define SM_AS    29696    // 2 bufs x 128 f32       (1024)
#define SM_BS    30720    // 2 bufs x 128 f32       (1024)
#define SM_A     31744    // 2 bufs x 128 rows x 80B (20480)
#define SM_B     52224    // 2 bufs x 128 rows x 80B (20480)
#define SMEM_TOT 72704

#define ABUF_BYTES 10240      // 128*80
#define BBUF_BYTES 10240      // 128*80

// ---------------- PTX helpers -------------------------------------------------
__device__ __forceinline__ uint32_t smem_u32(const void* p) {
    uint32_t a;
    asm("{ .reg .u64 t; cvta.to.shared.u64 t, %1; cvt.u32.u64 %0, t; }"
        : "=r"(a) : "l"(p));
    return a;
}
#define CP_ASYNC16(dst, src) \
    asm volatile("cp.async.cg.shared.global [%0], [%1], 16;" :: "r"(dst), "l"(src))
#define CP_COMMIT() asm volatile("cp.async.commit_group;" ::: "memory")
#define CP_WAIT1()  asm volatile("cp.async.wait_group 1;" ::: "memory")
#define CP_WAIT0()  asm volatile("cp.async.wait_group 0;" ::: "memory")

#define LDSM_X4(r0, r1, r2, r3, addr)                                        \
    asm volatile("ldmatrix.sync.aligned.m8n8.x4.shared.b16 {%0,%1,%2,%3}, [%4];" \
        : "=r"(r0), "=r"(r1), "=r"(r2), "=r"(r3) : "r"(addr))

// s8 IMMA k32, s32 accumulators
#define MMA_S8(d, a, b0, b1)                                                 \
    asm volatile("mma.sync.aligned.m16n8k32.row.col.s32.s8.s8.s32 "          \
        "{%0,%1,%2,%3}, {%4,%5,%6,%7}, {%8,%9}, {%0,%1,%2,%3};"              \
        : "+r"((d)[0]), "+r"((d)[1]), "+r"((d)[2]), "+r"((d)[3])             \
        : "r"((a)[0]), "r"((a)[1]), "r"((a)[2]), "r"((a)[3]),                \
          "r"(b0), "r"(b1))

// ---------------- init / prep ---------------------------------------------------
__global__ void init_kernel(const float* __restrict__ inputs)
{
    int i = blockIdx.x * blockDim.x + threadIdx.x;
    if (i < BB * NN * FI) {
        int f = i & 3;
        int row = i >> 2;
        float v = inputs[row * (11 * FI) + f];
        g_xst[i] = v;
        g_xarg[i] = v;
    }
}

// Quantize W2 per (k, chunk, n): 2-limb s8 with per-(chunk,col) scale.
__global__ void w2quant_kernel(const float* __restrict__ W2)
{
    int i = blockIdx.x * blockDim.x + threadIdx.x;   // 4096
    if (i >= 4096) return;
    int n = i & 255, ck = (i >> 8) & 7, k = i >> 11;
    float m = 0.f;
    for (int j = 0; j < 32; j++) {
        float w = W2[(size_t)(k * 256 + ck * 32 + j) * 256 + n];
        m = fmaxf(m, fabsf(w));
    }
    float inv = (m > 0.f) ? 127.0f / m : 0.f;
    char* dst = (char*)g_w2q + (size_t)i * 64;
    for (int j = 0; j < 32; j++) {
        float w = W2[(size_t)(k * 256 + ck * 32 + j) * 256 + n];
        float v = w * inv;
        int q1 = __float2int_rn(v);
        q1 = max(-127, min(127, q1));
        float r = v - (float)q1;
        int q0 = __float2int_rn(r * 254.0f);
        q0 = max(-127, min(127, q0));
        dst[j] = (char)q1;
        dst[32 + j] = (char)q0;
    }
    g_w2s[i] = m;
}

__global__ void wo_transpose_kernel(const float* __restrict__ Wo1,
                                    const float* __restrict__ Wo2)
{
    int i = blockIdx.x * blockDim.x + threadIdx.x;
    if (i < 256 * 264) {
        int col = i / 264, j = i % 264;
        g_wo1t[col * 264 + j] = (j < 260) ? Wo1[j * 256 + col] : 0.f;
    }
    if (i < 256 * 256) {
        int col = i >> 8, j = i & 255;
        g_wo2t[col * 256 + j] = Wo2[j * 256 + col];
    }
}

// ---------------- edge kernel: s8 IMMA, 2-limb split ------------------------------
// CTA = (batch, 2 receivers, N-half). M=128 rows (4 warps x 32), N=128 (2 warps x 64),
// K=256 hidden (x2 k-comp) in 16 chunks of 32 (one k32 IMMA step each).
__global__ __launch_bounds__(256, 1) void edge_mma_kernel(
    const float* __restrict__ edges,
    const float* __restrict__ W1g, const float* __restrict__ b1g,
    const float* __restrict__ b2g)
{
    extern __shared__ float s[];
    uint32_t sbase = smem_u32(s);
    const int t = threadIdx.x;
    const int wid = t >> 5, lane = t & 31;
    const int group = lane >> 2, tid4 = lane & 3;
    const int wm = wid & 3, wn = wid >> 2;          // 4 M-warps x 2 N-warps
    const int b = blockIdx.x >> 6;
    const int sub = blockIdx.x & 63;
    const int n0 = (sub >> 1) * 2;                  // receiver tile
    const int nh = sub & 1;                         // N half

    // ---- stage constants
    for (int i = t; i < 512; i += 256) {
        s[SM_B1 / 4 + i] = b1g[i];
        s[SM_B2 / 4 + i] = b2g[i];
    }
    for (int i = t; i < 4096; i += 256) s[SM_W1 / 4 + i] = W1g[i];
    if (t < 128) {
        int g = t >> 6, n = n0 + g, el = t & 63;
        float4 xs = make_float4(0.f, 0.f, 0.f, 0.f), xr = xs;
        float2 ew = make_float2(0.f, 0.f);
        if (el < EPN) {
            int send = (el < n) ? el : el + 1;
            xs = *(const float4*)(g_xarg + (b * NN + send) * 4);
            xr = *(const float4*)(g_xarg + (b * NN + n) * 4);
            ew = *(const float2*)(edges + ((long)(b * EE) + n * EPN + el) * 2);
        }
        float4* pr = (float4*)(s + SM_PRE / 4 + t * 8);
        pr[0] = xs; pr[1] = xr;
        s[SM_EW / 4 + t * 2 + 0] = ew.x;
        s[SM_EW / 4 + t * 2 + 1] = ew.y;
    }
    __syncthreads();

    // ---- staging: quantized W2 chunk (128 rows x 64B) + col scales
    auto stage_w2 = [&](int c, int buf) {
        int k = c >> 3, ck = c & 7;
        size_t ibase = (size_t)(k * 2048 + ck * 256 + nh * 128);
        const char* src = (const char*)g_w2q + ibase * 64;
        uint32_t db = sbase + SM_B + (uint32_t)buf * BBUF_BYTES;
        #pragma unroll
        for (int i = 0; i < 2; i++) {
            int idx = t + i * 256;            // 0..511
            int row = idx >> 2, seg = idx & 3;
            CP_ASYNC16(db + (uint32_t)(row * 80 + seg * 16),
                       src + row * 64 + seg * 16);
        }
        if (t < 32)
            CP_ASYNC16(sbase + SM_BS + (uint32_t)buf * 512u + (uint32_t)t * 16u,
                       (const char*)(g_w2s + ibase) + t * 16);
    };
    // ---- compute h chunk, quantize to 2-limb s8 with per-chunk row scale
    auto compute_h = [&](int c, int buf) {
        int k = c >> 3, ck = c & 7;
        int jp = t & 15, rg = t >> 4;
        int j0 = ck * 32 + 2 * jp;
        float w1a[8], w1b[8];
        #pragma unroll
        for (int f = 0; f < 8; f++) {
            w1a[f] = s[SM_W1 / 4 + (k * 8 + f) * 256 + j0];
            w1b[f] = s[SM_W1 / 4 + (k * 8 + f) * 256 + j0 + 1];
        }
        float b1a = s[SM_B1 / 4 + k * 256 + j0];
        float b1b = s[SM_B1 / 4 + k * 256 + j0 + 1];
        char* ab = (char*)s + SM_A + buf * ABUF_BYTES;
        float* as = s + SM_AS / 4 + buf * 128;
        #pragma unroll
        for (int rr = 0; rr < 8; rr++) {
            int r = rg * 8 + rr;
            const float4* pr = (const float4*)(s + SM_PRE / 4 + r * 8);
            float4 p0 = pr[0], p1 = pr[1];
            float h0 = b1a, h1 = b1b;
            h0 += p0.x * w1a[0]; h1 += p0.x * w1b[0];
            h0 += p0.y * w1a[1]; h1 += p0.y * w1b[1];
            h0 += p0.z * w1a[2]; h1 += p0.z * w1b[2];
            h0 += p0.w * w1a[3]; h1 += p0.w * w1b[3];
            h0 += p1.x * w1a[4]; h1 += p1.x * w1b[4];
            h0 += p1.y * w1a[5]; h1 += p1.y * w1b[5];
            h0 += p1.z * w1a[6]; h1 += p1.z * w1b[6];
            h0 += p1.w * w1a[7]; h1 += p1.w * w1b[7];
            h0 = fmaxf(h0, 0.f); h1 = fmaxf(h1, 0.f);
            // per-chunk row max over 16 lanes
            float mx = fmaxf(h0, h1);
            mx = fmaxf(mx, __shfl_xor_sync(0xffffffffu, mx, 1));
            mx = fmaxf(mx, __shfl_xor_sync(0xffffffffu, mx, 2));
            mx = fmaxf(mx, __shfl_xor_sync(0xffffffffu, mx, 4));
            mx = fmaxf(mx, __shfl_xor_sync(0xffffffffu, mx, 8));
            float inv = (mx > 0.f) ? 127.0f / mx : 0.f;
            float v0 = h0 * inv, v1 = h1 * inv;     // in [0,127]
            int q1a = __float2int_rn(v0);
            int q1b = __float2int_rn(v1);
            int q0a = __float2int_rn((v0 - (float)q1a) * 254.0f);
            int q0b = __float2int_rn((v1 - (float)q1b) * 254.0f);
            char* rowp = ab + r * 80;
            uint16_t hi = (uint16_t)((q1a & 0xff) | ((q1b & 0xff) << 8));
            uint16_t lo = (uint16_t)((q0a & 0xff) | ((q0b & 0xff) << 8));
            *(uint16_t*)(rowp + jp * 2)      = hi;
            *(uint16_t*)(rowp + 32 + jp * 2) = lo;
            if (jp == 0) as[r] = mx;
        }
    };

    float f32acc[2][8][4];
    #pragma unroll
    for (int m = 0; m < 2; m++)
        #pragma unroll
        for (int nt = 0; nt < 8; nt++)
            #pragma unroll
            for (int q = 0; q < 4; q++) f32acc[m][nt][q] = 0.f;

    // per-thread invariant fragment addresses (80B row stride)
    const uint32_t aRow = sbase + SM_A + (uint32_t)(wm * 32 + (lane & 15)) * 80u
                        + ((lane & 16) ? 16u : 0u);
    const uint32_t bRow = sbase + SM_B
                        + (uint32_t)(wn * 64 + (lane & 7) + ((lane >> 4) & 1) * 8) * 80u
                        + (uint32_t)((lane >> 3) & 1) * 16u;

    // prologue: chunk 0
    stage_w2(0, 0);
    CP_COMMIT();
    compute_h(0, 0);

    for (int c = 0; c < 16; c++) {
        int buf = c & 1;
        if (c < 15) {
            stage_w2(c + 1, 1 - buf);
            CP_COMMIT();
            compute_h(c + 1, 1 - buf);
            CP_WAIT1();
        } else {
            CP_WAIT0();
        }
        __syncthreads();

        const uint32_t aBuf = (uint32_t)buf * ABUF_BYTES;
        const uint32_t bBuf = (uint32_t)buf * BBUF_BYTES;

        // A limb fragments (k32): a1 and a0
        uint32_t a1f[2][4], a0f[2][4];
        #pragma unroll
        for (int mt = 0; mt < 2; mt++) {
            LDSM_X4(a1f[mt][0], a1f[mt][1], a1f[mt][2], a1f[mt][3],
                    aRow + aBuf + (uint32_t)mt * (16u * 80u));
            LDSM_X4(a0f[mt][0], a0f[mt][1], a0f[mt][2], a0f[mt][3],
                    aRow + aBuf + 32u + (uint32_t)mt * (16u * 80u));
        }
        // per-chunk scales
        float sa[2][2];
        {
            const float* as = s + SM_AS / 4 + buf * 128;
            int rb = wm * 32 + group;
            sa[0][0] = as[rb];      sa[0][1] = as[rb + 8];
            sa[1][0] = as[rb + 16]; sa[1][1] = as[rb + 24];
        }
        const float* bs = s + SM_BS / 4 + buf * 128;

        #pragma unroll
        for (int ntp = 0; ntp < 4; ntp++) {
            uint32_t b1f[4], b0f[4];
            LDSM_X4(b1f[0], b1f[1], b1f[2], b1f[3],
                    bRow + bBuf + (uint32_t)ntp * (16u * 80u));
            LDSM_X4(b0f[0], b0f[1], b0f[2], b0f[3],
                    bRow + bBuf + 32u + (uint32_t)ntp * (16u * 80u));
            int acc1[2][2][4], acc2[2][2][4];
            #pragma unroll
            for (int mt = 0; mt < 2; mt++)
                #pragma unroll
                for (int g = 0; g < 2; g++)
                    #pragma unroll
                    for (int q = 0; q < 4; q++) { acc1[mt][g][q] = 0; acc2[mt][g][q] = 0; }
            #pragma unroll
            for (int mt = 0; mt < 2; mt++) {
                MMA_S8(acc1[mt][0], a1f[mt], b1f[0], b1f[1]);
                MMA_S8(acc1[mt][1], a1f[mt], b1f[2], b1f[3]);
                MMA_S8(acc2[mt][0], a1f[mt], b0f[0], b0f[1]);
                MMA_S8(acc2[mt][1], a1f[mt], b0f[2], b0f[3]);
                MMA_S8(acc2[mt][0], a0f[mt], b1f[0], b1f[1]);
                MMA_S8(acc2[mt][1], a0f[mt], b1f[2], b1f[3]);
            }
            // convert with scales: val = acc1 + acc2/254; x sa*sb/127^2
            #pragma unroll
            for (int mt = 0; mt < 2; mt++)
                #pragma unroll
                for (int g = 0; g < 2; g++) {
                    int nt = 2 * ntp + g;
                    int c0 = wn * 64 + nt * 8 + tid4 * 2;
                    float sb0 = bs[c0]     * (1.0f / 16129.0f);
                    float sb1 = bs[c0 + 1] * (1.0f / 16129.0f);
                    #pragma unroll
                    for (int q = 0; q < 4; q++) {
                        float val = (float)acc1[mt][g][q]
                                  + (float)acc2[mt][g][q] * (1.0f / 254.0f);
                        float sc = sa[mt][q >> 1] * ((q & 1) ? sb1 : sb0);
                        f32acc[mt][nt][q] += sc * val;
                    }
                }
        }

        // ---- epilogue for this k-component after its last chunk
        if ((c & 7) == 7) {
            int k = c >> 3;
            float colsum[16];
            #pragma unroll
            for (int i = 0; i < 16; i++) colsum[i] = 0.f;
            #pragma unroll
            for (int m = 0; m < 2; m++) {
                int rbase = wm * 32 + m * 16 + group;
                float ew0 = s[SM_EW / 4 + rbase * 2 + k];
                float ew1 = s[SM_EW / 4 + (rbase + 8) * 2 + k];
                #pragma unroll
                for (int nt = 0; nt < 8; nt++) {
                    int col0 = nh * 128 + wn * 64 + nt * 8 + tid4 * 2;
                    float bz0 = s[SM_B2 / 4 + k * 256 + col0];
                    float bz1 = s[SM_B2 / 4 + k * 256 + col0 + 1];
                    colsum[nt * 2 + 0] += fmaxf(f32acc[m][nt][0] + bz0, 0.f) * ew0
                                        + fmaxf(f32acc[m][nt][2] + bz0, 0.f) * ew1;
                    colsum[nt * 2 + 1] += fmaxf(f32acc[m][nt][1] + bz1, 0.f) * ew0
                                        + fmaxf(f32acc[m][nt][3] + bz1, 0.f) * ew1;
                }
            }
            #pragma unroll
            for (int off = 4; off <= 16; off <<= 1)
                #pragma unroll
                for (int i = 0; i < 16; i++)
                    colsum[i] += __shfl_xor_sync(0xffffffffu, colsum[i], off);
            if (lane < 4) {
                float* dst = s + SM_PART / 4 + (k * 4 + wm) * 128 + wn * 64;
                #pragma unroll
                for (int nt = 0; nt < 8; nt++) {
                    dst[nt * 8 + lane * 2 + 0] = colsum[nt * 2 + 0];
                    dst[nt * 8 + lane * 2 + 1] = colsum[nt * 2 + 1];
                }
            }
            #pragma unroll
            for (int m = 0; m < 2; m++)
                #pragma unroll
                for (int nt = 0; nt < 8; nt++)
                    #pragma unroll
                    for (int q = 0; q < 4; q++) f32acc[m][nt][q] = 0.f;
        }
        __syncthreads();
    }

    // ---- final aggregation across k and M-warps (2 receivers x 128 cols)
    {
        const float* p = s + SM_PART / 4;
        int recv = t >> 7, col = t & 127;
        float v = p[(recv * 2 + 0) * 128 + col] + p[(recv * 2 + 1) * 128 + col]
                + p[(4 + recv * 2 + 0) * 128 + col] + p[(4 + recv * 2 + 1) * 128 + col];
        g_agg[(b * NN + n0 + recv) * 256 + nh * 128 + col] = v;
    }
}

// ---------------- node kernel: output MLP + RK4, vectorized transposed weights --
#define NROWS 16
__global__ __launch_bounds__(256) void node_kernel(
    const float* __restrict__ bo1, const float* __restrict__ bo2,
    const float* __restrict__ Wo3, const float* __restrict__ bo3,
    float* __restrict__ outp, int stage, int step)
{
    __shared__ float s_a[NROWS][264];
    __shared__ float s_h[NROWS][264];

    int r0 = blockIdx.x * NROWS;
    int t = threadIdx.x;

    for (int i = t; i < NROWS * 264; i += 256) {
        int r = i / 264, c = i % 264;
        int row = r0 + r;
        float v = 0.f;
        if (c < 4) v = g_xarg[row * 4 + c];
        else if (c < 260) v = g_agg[row * 256 + (c - 4)];
        s_a[r][c] = v;
    }
    __syncthreads();

    float acc[NROWS];

    {
        float bv = bo1[t];
        #pragma unroll
        for (int r = 0; r < NROWS; r++) acc[r] = bv;
    }
    {
        const float4* wrow = (const float4*)(g_wo1t + t * 264);
        float4 w0 = __ldg(&wrow[0]);
        float4 w1 = __ldg(&wrow[1]);
        #pragma unroll 2
        for (int it = 0; it < 66; it++) {
            float4 cw = (it & 1) ? w1 : w0;
            int jn = it + 2;
            if (jn < 66) {
                if (it & 1) w1 = __ldg(&wrow[jn]);
                else        w0 = __ldg(&wrow[jn]);
            }
            int j = it * 4;
            #pragma unroll
            for (int r = 0; r < NROWS; r++) {
                float4 a4 = *(const float4*)&s_a[r][j];
                acc[r] += a4.x * cw.x + a4.y * cw.y + a4.z * cw.z + a4.w * cw.w;
            }
        }
    }
    #pragma unroll
    for (int r = 0; r < NROWS; r++) s_h[r][t] = fmaxf(acc[r], 0.f);
    __syncthreads();

    {
        float bv = bo2[t];
        #pragma unroll
        for (int r = 0; r < NROWS; r++) acc[r] = bv;
    }
    {
        const float4* wrow = (const float4*)(g_wo2t + t * 256);
        float4 w0 = __ldg(&wrow[0]);
        float4 w1 = __ldg(&wrow[1]);
        #pragma unroll 2
        for (int it = 0; it < 64; it++) {
            float4 cw = (it & 1) ? w1 : w0;
            int jn = it + 2;
            if (jn < 64) {
                if (it & 1) w1 = __ldg(&wrow[jn]);
                else        w0 = __ldg(&wrow[jn]);
            }
            int j = it * 4;
            #pragma unroll
            for (int r = 0; r < NROWS; r++) {
                float4 a4 = *(const float4*)&s_h[r][j];
                acc[r] += a4.x * cw.x + a4.y * cw.y + a4.z * cw.z + a4.w * cw.w;
            }
        }
    }
    __syncthreads();
    #pragma unroll
    for (int r = 0; r < NROWS; r++) s_a[r][t] = fmaxf(acc[r], 0.f);
    __syncthreads();

    int wr = t >> 5, lane = t & 31;
    #pragma unroll
    for (int rr = 0; rr < 2; rr++) {
        int rl = wr * 2 + rr;
        float4 pf = make_float4(0.f, 0.f, 0.f, 0.f);
        for (int j = lane; j < 256; j += 32) {
            float v = s_a[rl][j];
            float4 w3 = *(const float4*)(Wo3 + j * 4);
            pf.x += v * w3.x; pf.y += v * w3.y;
            pf.z += v * w3.z; pf.w += v * w3.w;
        }
        #pragma unroll
        for (int off = 16; off; off >>= 1) {
            pf.x += __shfl_xor_sync(0xffffffffu, pf.x, off);
            pf.y += __shfl_xor_sync(0xffffffffu, pf.y, off);
            pf.z += __shfl_xor_sync(0xffffffffu, pf.z, off);
            pf.w += __shfl_xor_sync(0xffffffffu, pf.w, off);
        }

        if (lane == 0) {
            int row = r0 + rl;
            float dt = (float)(step + 1) / 10.0f - (float)step / 10.0f;

            float4 xa = *(const float4*)(g_xarg + row * 4);
            float4 xs = *(const float4*)(g_xst + row * 4);

            float4 ko;
            ko.x = xa.x + pf.x + bo3[0];
            ko.y = xa.y + pf.y + bo3[1];
            ko.z = xa.z + pf.z + bo3[2];
            ko.w = xa.w + pf.w + bo3[3];

            float4 ka;
            if (stage == 0) {
                ka = ko;
            } else {
                ka = *(const float4*)(g_kacc + row * 4);
                float sc = (stage == 3) ? 1.0f : 2.0f;
                ka.x += sc * ko.x; ka.y += sc * ko.y;
                ka.z += sc * ko.z; ka.w += sc * ko.w;
            }

            if (stage < 3) {
                *(float4*)(g_kacc + row * 4) = ka;
                float cc = (stage == 2) ? dt : 0.5f * dt;
                float4 xn;
                xn.x = xs.x + cc * ko.x; xn.y = xs.y + cc * ko.y;
                xn.z = xs.z + cc * ko.z; xn.w = xs.w + cc * ko.w;
                *(float4*)(g_xarg + row * 4) = xn;
            } else {
                float cc = dt * (1.0f / 6.0f);
                float4 xn;
                xn.x = xs.x + cc * ka.x; xn.y = xs.y + cc * ka.y;
                xn.z = xs.z + cc * ka.z; xn.w = xs.w + cc * ka.w;
                *(float4*)(g_xst + row * 4) = xn;
                *(float4*)(g_xarg + row * 4) = xn;
                *(float4*)(outp + (row * NSTEP + step) * 4) = xn;
            }
        }
    }
}

// ---------------- launch ------------------------------------------------------
extern "C" void kernel_launch(void* const* d_in, const int* in_sizes, int n_in,
                              void* d_out, int out_size)
{
    const float* inputs = (const float*)d_in[0];
    const float* edges  = (const float*)d_in[1];
    const float* W1  = (const float*)d_in[4];
    const float* b1  = (const float*)d_in[5];
    const float* W2  = (const float*)d_in[6];
    const float* b2  = (const float*)d_in[7];
    const float* Wo1 = (const float*)d_in[8];
    const float* bo1 = (const float*)d_in[9];
    const float* Wo2 = (const float*)d_in[10];
    const float* bo2 = (const float*)d_in[11];
    const float* Wo3 = (const float*)d_in[12];
    const float* bo3 = (const float*)d_in[13];
    float* outp = (float*)d_out;

    cudaFuncSetAttribute(edge_mma_kernel,
                         cudaFuncAttributeMaxDynamicSharedMemorySize, SMEM_TOT);

    init_kernel<<<(BB * NN * FI + 255) / 256, 256>>>(inputs);
    w2quant_kernel<<<16, 256>>>(W2);
    wo_transpose_kernel<<<(256 * 264 + 255) / 256, 256>>>(Wo1, Wo2);

    for (int step = 0; step < NSTEP; step++) {
        for (int stage = 0; stage < 4; stage++) {
            edge_mma_kernel<<<BB * 64, 256, SMEM_TOT>>>(edges, W1, b1, b2);
            node_kernel<<<BB * NN / NROWS, 256>>>(bo1, bo2, Wo3, bo3,
                                                  outp, stage, step);
        }
    }
}